// round 14
// baseline (speedup 1.0000x reference)
#include <cuda_runtime.h>
#include <math.h>
#include <stdint.h>

#define BOARD   13
#define NN      169
#define NNP     176         // padded node rows (11 x 16 for m16 tiles)
#define DIM     128
#define SROW    132         // h/hbar row stride in floats (528B: conflict-free frags)
#define WROW    136         // weight row stride in floats (544B: conflict-free frags)
#define CHN     8
#define NLAYERS 8
#define NBW     11          // gather/embed: max nodes per warp

// Pre-split fused weights, chunked: Wall[l][c][2][8][WROW] where c = 8-k-row
// chunk (32 per layer; k 0-127 = upd_w top half, 128-255 = Wcomb), [0]=tf32-hi
// rows, [1]=tf32-lo rows. One chunk = 2176 floats (8704 B).
#define CHUNK_F 2176
__device__ float Wall_g[NLAYERS * 32 * CHUNK_F];

struct Smem {
    float h[NNP * SROW];      // 92928 B
    float hbar[NNP * SROW];   // 92928 B
    float wbuf[3][CHUNK_F];   // 26112 B (triple buffer)
    int   nbr[NN * 6];
    int   cnt[NN];
    float invdeg[NN];
    float slog[NN];
    float lnpart[NNP * 8];    // [row][ng*2 + {sum,sumsq}]
    float gpart[4 * DIM];
    float gvec[DIM];
    float uvec[256];
    float redall[8];
    float scal[2];
};                            // ~227.3 KB < 232448 B cap

__device__ __forceinline__ float gelu_f(float x) {
    return 0.5f * x * (1.0f + erff(x * 0.70710678118654752440f));
}

__device__ __forceinline__ void cp16(const float* smem_dst, const float* gsrc) {
    uint32_t s = (uint32_t)__cvta_generic_to_shared(smem_dst);
    asm volatile("cp.async.cg.shared.global [%0], [%1], 16;" :: "r"(s), "l"(gsrc));
}

// one 2176-float chunk with 512 threads (544 cp16 ops)
__device__ __forceinline__ void load_chunk(float* dst, const float* src, int tid) {
    cp16(dst + tid * 4, src + tid * 4);
    if (tid < 32) cp16(dst + 2048 + tid * 4, src + 2048 + tid * 4);
    asm volatile("cp.async.commit_group;" ::: "memory");
}

__device__ __forceinline__ void split_tf32(float x, uint32_t& hi, uint32_t& lo) {
    uint32_t u = __float_as_uint(x) & 0xffffe000u;
    float l = x - __uint_as_float(u);
    hi = u;
    lo = __float_as_uint(l) & 0xffffe000u;
}

__device__ __forceinline__ void mma8(float& d0, float& d1, float& d2, float& d3,
                                     uint32_t a0, uint32_t a1, uint32_t a2, uint32_t a3,
                                     uint32_t b0, uint32_t b1) {
    asm volatile(
        "mma.sync.aligned.m16n8k8.row.col.f32.tf32.tf32.f32 "
        "{%0,%1,%2,%3}, {%4,%5,%6,%7}, {%8,%9}, {%0,%1,%2,%3};"
        : "+f"(d0), "+f"(d1), "+f"(d2), "+f"(d3)
        : "r"(a0), "r"(a1), "r"(a2), "r"(a3), "r"(b0), "r"(b1));
}

// prep: build fused weights + pre-split into tf32 hi/lo chunk layout
__global__ void prep(const float* __restrict__ msg_w,
                     const float* __restrict__ upd_w) {
    const int kk = blockIdx.x, l = blockIdx.y, d = threadIdx.x;  // d = out col
    float v;
    if (kk < DIM) {
        v = upd_w[l * 2 * DIM * DIM + kk * DIM + d];
    } else {
        const float* M = msg_w + (l * DIM + (kk - DIM)) * DIM;
        const float* U2 = upd_w + l * 2 * DIM * DIM + DIM * DIM;
        v = 0.f;
        #pragma unroll 4
        for (int k = 0; k < DIM; k++) v = fmaf(M[k], U2[k * DIM + d], v);
    }
    uint32_t hi, lo;
    split_tf32(v, hi, lo);
    const int c = kk >> 3, kr = kk & 7;
    float* base = Wall_g + (l * 32 + c) * CHUNK_F;
    base[kr * WROW + d]        = __uint_as_float(hi);
    base[1088 + kr * WROW + d] = __uint_as_float(lo);
}

__global__ __launch_bounds__(512, 1)
void hexgnn_kernel(const float* __restrict__ x,
                   const float* __restrict__ in_w,  const float* __restrict__ in_b,
                   const float* __restrict__ in_g,  const float* __restrict__ in_beta,
                   const float* __restrict__ upd_b, const float* __restrict__ ln_g,
                   const float* __restrict__ ln_b,  const float* __restrict__ aq_w,
                   const float* __restrict__ aq_b,  const float* __restrict__ pp_w,
                   const float* __restrict__ pp_b,  const float* __restrict__ v1_w,
                   const float* __restrict__ v1_b,  const float* __restrict__ v2_w,
                   const float* __restrict__ v2_b,  const float* __restrict__ tf_w,
                   const float* __restrict__ tf_b,  float* __restrict__ out) {
    extern __shared__ char smraw[];
    Smem& sm = *reinterpret_cast<Smem*>(smraw);

    const int tid  = threadIdx.x;
    const int lane = tid & 31;
    const int warp = tid >> 5;
    const int qr   = lane >> 2;          // fragment groupID
    const int qc   = lane & 3;           // fragment threadID-in-group
    const int d0   = lane * 4;           // gather/embed: 4 cols per thread
    const int b    = blockIdx.x;
    const int B    = gridDim.x;
    // gather/embed node partition: warps 0-8 own 11, 9-15 own 10 (169 total)
    const int base = (warp < 9) ? warp * 11 : 99 + (warp - 9) * 10;
    const int ncnt = (warp < 9) ? 11 : 10;
    // mma tiles: t = warp + 16s; m-slab = t%11, n-group = t/11 (44 tiles)
    const int tcount = (warp < 12) ? 3 : 2;

    int rowoff[NBW];
    #pragma unroll
    for (int j = 0; j < NBW; j++) {
        int n = base + j; if (n > NN - 1) n = NN - 1;
        rowoff[j] = n * SROW;
    }

    // ---- adjacency tables + pad-row zeroing ----
    if (tid < NN) {
        const int i = tid / BOARD, j = tid % BOARD;
        const int di[6] = {1, -1, 0, 0, 1, -1};
        const int dj[6] = {0, 0, 1, -1, -1, 1};
        int cc = 0;
        for (int e = 0; e < 6; e++) {
            int ni = i + di[e], nj = j + dj[e];
            if (ni >= 0 && ni < BOARD && nj >= 0 && nj < BOARD)
                sm.nbr[tid * 6 + (cc++)] = ni * BOARD + nj;
        }
        sm.cnt[tid] = cc;
        sm.invdeg[tid] = 1.0f / (float)cc;
    }
    for (int i = tid; i < (NNP - NN) * SROW; i += 512) {   // zero pad rows once
        sm.h[NN * SROW + i] = 0.f;
        sm.hbar[NN * SROW + i] = 0.f;
    }

    // ---- input embedding: h = LN(gelu(x @ in_w + in_b)) ----
    {
        const float* xb = x + (size_t)b * CHN * NN;
        const float4 bi4 = *(const float4*)(in_b + d0);
        const float4 gg4 = *(const float4*)(in_g + d0);
        const float4 be4 = *(const float4*)(in_beta + d0);
        #pragma unroll 1
        for (int j = 0; j < NBW; j++) {
            if (j >= ncnt) break;
            const int n = (base + j);
            float a0 = bi4.x, a1 = bi4.y, a2 = bi4.z, a3 = bi4.w;
            #pragma unroll
            for (int ch = 0; ch < CHN; ch++) {
                const float xv = __ldg(xb + ch * NN + n);
                const float4 w = *(const float4*)(in_w + ch * DIM + d0);
                a0 = fmaf(xv, w.x, a0); a1 = fmaf(xv, w.y, a1);
                a2 = fmaf(xv, w.z, a2); a3 = fmaf(xv, w.w, a3);
            }
            float v0 = gelu_f(a0), v1 = gelu_f(a1), v2 = gelu_f(a2), v3 = gelu_f(a3);
            float ss = v0 + v1 + v2 + v3;
            float qq = v0*v0 + v1*v1 + v2*v2 + v3*v3;
            #pragma unroll
            for (int o = 16; o; o >>= 1) {
                ss += __shfl_xor_sync(0xffffffffu, ss, o);
                qq += __shfl_xor_sync(0xffffffffu, qq, o);
            }
            const float mu  = ss * (1.0f / DIM);
            const float var = qq * (1.0f / DIM) - mu * mu;
            const float rs  = rsqrtf(var + 1e-5f);
            *(float4*)(sm.h + rowoff[j] + d0) = make_float4(
                (v0 - mu) * rs * gg4.x + be4.x, (v1 - mu) * rs * gg4.y + be4.y,
                (v2 - mu) * rs * gg4.z + be4.z, (v3 - mu) * rs * gg4.w + be4.w);
        }
    }

    // ---- 8 GNN layers ----
    for (int l = 0; l < NLAYERS; l++) {
        __syncthreads();                              // h complete (cross-warp gather)

        const float* WL = Wall_g + l * 32 * CHUNK_F;
        load_chunk(sm.wbuf[0], WL, tid);              // chunks 0,1 (overlap gather)
        load_chunk(sm.wbuf[1], WL + CHUNK_F, tid);

        // neighbor-mean gather into hbar (own rows only)
        #pragma unroll 1
        for (int j = 0; j < NBW; j++) {
            if (j >= ncnt) break;
            const int n = base + j;
            const int c = sm.cnt[n];
            const int* nb = sm.nbr + n * 6;
            float s0 = 0.f, s1 = 0.f, s2 = 0.f, s3 = 0.f;
            for (int e = 0; e < c; e++) {
                const float4 m = *(const float4*)(sm.h + nb[e] * SROW + d0);
                s0 += m.x; s1 += m.y; s2 += m.z; s3 += m.w;
            }
            const float id = sm.invdeg[n];
            *(float4*)(sm.hbar + rowoff[j] + d0) =
                make_float4(s0 * id, s1 * id, s2 * id, s3 * id);
        }

        // ---- tensor-core GEMM: D[176 x 128] = [h|hbar] @ Wall, 3xTF32 ----
        float acc[3][4][4];
        #pragma unroll
        for (int s = 0; s < 3; s++)
            #pragma unroll
            for (int nt = 0; nt < 4; nt++)
                #pragma unroll
                for (int i = 0; i < 4; i++) acc[s][nt][i] = 0.f;

        #pragma unroll 1
        for (int c = 0; c < 32; c++) {
            if (c == 31) asm volatile("cp.async.wait_group 0;" ::: "memory");
            else         asm volatile("cp.async.wait_group 1;" ::: "memory");
            __syncthreads();                  // chunk c visible; (c=0) gathers done
            if (c < 30) load_chunk(sm.wbuf[(c + 2) % 3], WL + (c + 2) * CHUNK_F, tid);

            const float* asrc = (c < 16) ? sm.h : sm.hbar;
            const int klocal = (c & 15) * 8;
            const float* wb = sm.wbuf[c % 3];

            #pragma unroll
            for (int s = 0; s < 3; s++) {
                if (s < tcount) {
                    const int t = warp + 16 * s;
                    const int m = t % 11, ng = t / 11;
                    const float* ap = asrc + (m * 16 + qr) * SROW + klocal + qc;
                    uint32_t ah0, ah1, ah2, ah3, al0, al1, al2, al3;
                    split_tf32(ap[0],            ah0, al0);
                    split_tf32(ap[8 * SROW],     ah1, al1);
                    split_tf32(ap[4],            ah2, al2);
                    split_tf32(ap[8 * SROW + 4], ah3, al3);
                    const float* bph = wb + qc * WROW + ng * 32 + qr;
                    const float* bpl = bph + 1088;
                    #pragma unroll
                    for (int nt = 0; nt < 4; nt++) {
                        const uint32_t bh0 = __float_as_uint(bph[nt * 8]);
                        const uint32_t bh1 = __float_as_uint(bph[nt * 8 + 4 * WROW]);
                        const uint32_t bl0 = __float_as_uint(bpl[nt * 8]);
                        const uint32_t bl1 = __float_as_uint(bpl[nt * 8 + 4 * WROW]);
                        mma8(acc[s][nt][0], acc[s][nt][1], acc[s][nt][2], acc[s][nt][3],
                             ah0, ah1, ah2, ah3, bh0, bh1);
                        mma8(acc[s][nt][0], acc[s][nt][1], acc[s][nt][2], acc[s][nt][3],
                             ah0, ah1, ah2, ah3, bl0, bl1);
                        mma8(acc[s][nt][0], acc[s][nt][1], acc[s][nt][2], acc[s][nt][3],
                             al0, al1, al2, al3, bh0, bh1);
                    }
                }
            }
        }

        // ---- epilogue A: v = gelu(acc + bias) + h; per-node partials ----
        const float* ub = upd_b + l * DIM;
        #pragma unroll
        for (int s = 0; s < 3; s++) {
            if (s < tcount) {
                const int t = warp + 16 * s;
                const int m = t % 11, ng = t / 11;
                const int rlo = m * 16 + qr, rhi = rlo + 8;
                float sLo = 0.f, qLo = 0.f, sHi = 0.f, qHi = 0.f;
                #pragma unroll
                for (int nt = 0; nt < 4; nt++) {
                    const int c0 = ng * 32 + nt * 8 + qc * 2, c1 = c0 + 1;
                    const float u0 = __ldg(ub + c0), u1 = __ldg(ub + c1);
                    float v0 = gelu_f(acc[s][nt][0] + u0) + sm.h[rlo * SROW + c0];
                    float v1 = gelu_f(acc[s][nt][1] + u1) + sm.h[rlo * SROW + c1];
                    float v2 = gelu_f(acc[s][nt][2] + u0) + sm.h[rhi * SROW + c0];
                    float v3 = gelu_f(acc[s][nt][3] + u1) + sm.h[rhi * SROW + c1];
                    acc[s][nt][0] = v0; acc[s][nt][1] = v1;
                    acc[s][nt][2] = v2; acc[s][nt][3] = v3;
                    sLo += v0 + v1; qLo += v0 * v0 + v1 * v1;
                    sHi += v2 + v3; qHi += v2 * v2 + v3 * v3;
                }
                #pragma unroll
                for (int o = 1; o <= 2; o <<= 1) {   // reduce across quad (qc)
                    sLo += __shfl_xor_sync(0xffffffffu, sLo, o);
                    qLo += __shfl_xor_sync(0xffffffffu, qLo, o);
                    sHi += __shfl_xor_sync(0xffffffffu, sHi, o);
                    qHi += __shfl_xor_sync(0xffffffffu, qHi, o);
                }
                if (qc == 0) {
                    sm.lnpart[rlo * 8 + ng * 2]     = sLo;
                    sm.lnpart[rlo * 8 + ng * 2 + 1] = qLo;
                    sm.lnpart[rhi * 8 + ng * 2]     = sHi;
                    sm.lnpart[rhi * 8 + ng * 2 + 1] = qHi;
                }
            }
        }
        __syncthreads();                              // partials complete

        // ---- epilogue B: LayerNorm normalize + write h ----
        const float* lg = ln_g + l * DIM;
        const float* lb = ln_b + l * DIM;
        #pragma unroll
        for (int s = 0; s < 3; s++) {
            if (s < tcount) {
                const int t = warp + 16 * s;
                const int m = t % 11, ng = t / 11;
                const int rlo = m * 16 + qr, rhi = rlo + 8;
                const float* pl = sm.lnpart + rlo * 8;
                const float* ph = sm.lnpart + rhi * 8;
                const float sLo = pl[0] + pl[2] + pl[4] + pl[6];
                const float qLo = pl[1] + pl[3] + pl[5] + pl[7];
                const float sHi = ph[0] + ph[2] + ph[4] + ph[6];
                const float qHi = ph[1] + ph[3] + ph[5] + ph[7];
                const float muL = sLo * (1.0f / DIM);
                const float rsL = rsqrtf(qLo * (1.0f / DIM) - muL * muL + 1e-5f);
                const float muH = sHi * (1.0f / DIM);
                const float rsH = rsqrtf(qHi * (1.0f / DIM) - muH * muH + 1e-5f);
                #pragma unroll
                for (int nt = 0; nt < 4; nt++) {
                    const int c0 = ng * 32 + nt * 8 + qc * 2, c1 = c0 + 1;
                    const float g0 = __ldg(lg + c0), g1 = __ldg(lg + c1);
                    const float b0 = __ldg(lb + c0), b1 = __ldg(lb + c1);
                    if (rlo < NN) {
                        sm.h[rlo * SROW + c0] = (acc[s][nt][0] - muL) * rsL * g0 + b0;
                        sm.h[rlo * SROW + c1] = (acc[s][nt][1] - muL) * rsL * g1 + b1;
                    }
                    if (rhi < NN) {
                        sm.h[rhi * SROW + c0] = (acc[s][nt][2] - muH) * rsH * g0 + b0;
                        sm.h[rhi * SROW + c1] = (acc[s][nt][3] - muH) * rsH * g1 + b1;
                    }
                }
            }
        }
    }
    __syncthreads();

    // ---- heads ----
    float* p_out = out;
    float* v_out = out + (size_t)B * NN;
    float* t_out = v_out + B;
    const float ppb = pp_b[0], aqb = aq_b[0], v2b = v2_b[0];

    for (int n = warp; n < NN; n += 16) {              // p + attention logits
        float hp = 0.f, ha = 0.f;
        #pragma unroll
        for (int i = 0; i < 4; i++) {
            const int dd = i * 32 + lane;
            const float hv = sm.h[n * SROW + dd];
            hp = fmaf(hv, pp_w[dd], hp);
            ha = fmaf(hv, aq_w[dd], ha);
        }
        #pragma unroll
        for (int o = 16; o; o >>= 1) {
            hp += __shfl_xor_sync(0xffffffffu, hp, o);
            ha += __shfl_xor_sync(0xffffffffu, ha, o);
        }
        if (lane == 0) { p_out[(size_t)b * NN + n] = hp + ppb; sm.slog[n] = ha + aqb; }
    }
    __syncthreads();
    if (warp == 0) {                                   // softmax max
        float m = -3.4e38f;
        for (int n = lane; n < NN; n += 32) m = fmaxf(m, sm.slog[n]);
        #pragma unroll
        for (int o = 16; o; o >>= 1) m = fmaxf(m, __shfl_xor_sync(0xffffffffu, m, o));
        if (lane == 0) sm.scal[0] = m;
    }
    __syncthreads();
    if (tid < NN) sm.slog[tid] = expf(sm.slog[tid] - sm.scal[0]);
    __syncthreads();
    if (warp == 0) {                                   // softmax Z
        float z = 0.f;
        for (int n = lane; n < NN; n += 32) z += sm.slog[n];
        #pragma unroll
        for (int o = 16; o; o >>= 1) z += __shfl_xor_sync(0xffffffffu, z, o);
        if (lane == 0) sm.scal[1] = z;
    }
    __syncthreads();
    {                                                  // g = sum_n h[n] * attn[n]
        const int q = tid >> 7, dc = tid & 127;
        const int ns = (q == 0) ? 0 : 43 + (q - 1) * 42;
        const int ne = ns + ((q == 0) ? 43 : 42);
        float gp = 0.f;
        for (int n = ns; n < ne; n++) gp = fmaf(sm.h[n * SROW + dc], sm.slog[n], gp);
        sm.gpart[q * DIM + dc] = gp;
    }
    __syncthreads();
    if (tid < DIM)
        sm.gvec[tid] = (sm.gpart[tid] + sm.gpart[DIM + tid] +
                        sm.gpart[2 * DIM + tid] + sm.gpart[3 * DIM + tid]) / sm.scal[1];
    __syncthreads();
    if (tid < 256) {                                   // v1
        float u = v1_b[tid];
        #pragma unroll 4
        for (int k = 0; k < DIM; k++) u = fmaf(sm.gvec[k], v1_w[k * 256 + tid], u);
        sm.uvec[tid] = gelu_f(u);
    }
    __syncthreads();
    if (tid < 256) {                                   // v2 reduce
        float pv = sm.uvec[tid] * v2_w[tid];
        #pragma unroll
        for (int o = 16; o; o >>= 1) pv += __shfl_xor_sync(0xffffffffu, pv, o);
        if (lane == 0) sm.redall[warp] = pv;
    }
    __syncthreads();
    if (tid == 0) {
        float sv = 0.f;
        #pragma unroll
        for (int w = 0; w < 8; w++) sv += sm.redall[w];
        v_out[b] = tanhf(sv + v2b);
    }
    if (warp < 4) {                                    // t head
        float tp = 0.f;
        #pragma unroll
        for (int i = 0; i < 4; i++) {
            const int dd = i * 32 + lane;
            tp = fmaf(sm.gvec[dd], tf_w[dd * 4 + warp], tp);
        }
        #pragma unroll
        for (int o = 16; o; o >>= 1) tp += __shfl_xor_sync(0xffffffffu, tp, o);
        if (lane == 0) t_out[(size_t)b * 4 + warp] = tp + tf_b[warp];
    }
}

extern "C" void kernel_launch(void* const* d_in, const int* in_sizes, int n_in,
                              void* d_out, int out_size) {
    const float* x       = (const float*)d_in[0];
    // d_in[1]=src, d_in[2]=dst: fixed hex adjacency, recomputed in-kernel
    const float* in_w    = (const float*)d_in[3];
    const float* in_b    = (const float*)d_in[4];
    const float* in_g    = (const float*)d_in[5];
    const float* in_beta = (const float*)d_in[6];
    const float* msg_w   = (const float*)d_in[7];
    const float* upd_w   = (const float*)d_in[8];
    const float* upd_b   = (const float*)d_in[9];
    const float* ln_g    = (const float*)d_in[10];
    const float* ln_b    = (const float*)d_in[11];
    const float* aq_w    = (const float*)d_in[12];
    const float* aq_b    = (const float*)d_in[13];
    const float* pp_w    = (const float*)d_in[14];
    const float* pp_b    = (const float*)d_in[15];
    const float* v1_w    = (const float*)d_in[16];
    const float* v1_b    = (const float*)d_in[17];
    const float* v2_w    = (const float*)d_in[18];
    const float* v2_b    = (const float*)d_in[19];
    const float* tf_w    = (const float*)d_in[20];
    const float* tf_b    = (const float*)d_in[21];
    float* out = (float*)d_out;

    const int B = in_sizes[0] / (CHN * NN);   // 512

    prep<<<dim3(256, NLAYERS), DIM>>>(msg_w, upd_w);

    const size_t smem = sizeof(Smem);
    cudaFuncSetAttribute(hexgnn_kernel, cudaFuncAttributeMaxDynamicSharedMemorySize,
                         (int)smem);
    hexgnn_kernel<<<B, 512, smem>>>(x, in_w, in_b, in_g, in_beta, upd_b,
                                    ln_g, ln_b, aq_w, aq_b, pp_w, pp_b, v1_w, v1_b,
                                    v2_w, v2_b, tf_w, tf_b, out);
}

// round 15
// speedup vs baseline: 1.1438x; 1.1438x over previous
#include <cuda_runtime.h>
#include <math.h>
#include <stdint.h>

#define BOARD   13
#define NN      169
#define NNP     176         // padded node rows (11 x 16 for m16 tiles)
#define DIM     128
#define SROW    132         // h/hbar row stride in floats (528B: conflict-free frags)
#define WROW    136         // weight row stride in floats (544B: conflict-free frags)
#define CHN     8
#define NLAYERS 8
#define NBW     11          // gather/embed: max nodes per warp

// Pre-split fused weights: Wall[l][c] = one 16-k-row chunk, laid out as
// [16 rows of tf32-hi][16 rows of tf32-lo], each row WROW floats.
// k 0-127 = upd_w top half, k 128-255 = Wcomb = msg_w[l] @ upd_w[l][128:256,:].
#define CHUNK_F 4352          // 32 * WROW floats = 17408 B
#define HALF_F  2176          // 16 * WROW (hi block size)
__device__ float Wall_g[NLAYERS * 16 * CHUNK_F];

struct Smem {
    float h[NNP * SROW];      // 92928 B
    float hbar[NNP * SROW];   // 92928 B
    union {                   // 34816 B: weight double-buffer / heads scratch
        float wbuf[2][CHUNK_F];
        struct {
            float slog[NN];
            float gpart[4 * DIM];
            float gvec[DIM];
            float uvec[256];
            float redall[8];
            float scal[2];
        } hd;
    } u;
    int   nbr[NN * 6];
    int   cnt[NN];
    float invdeg[NN];
    float lnpart[NNP * 8];    // [row][ng*2 + {sum,sumsq}]
};                            // 231712 B < 232448 B cap

__device__ __forceinline__ float gelu_f(float x) {
    return 0.5f * x * (1.0f + erff(x * 0.70710678118654752440f));
}

__device__ __forceinline__ void cp16(const float* smem_dst, const float* gsrc) {
    uint32_t s = (uint32_t)__cvta_generic_to_shared(smem_dst);
    asm volatile("cp.async.cg.shared.global [%0], [%1], 16;" :: "r"(s), "l"(gsrc));
}

// one 4352-float chunk with 512 threads (1088 cp16 ops)
__device__ __forceinline__ void load_chunk(float* dst, const float* src, int tid) {
    cp16(dst + tid * 4,          src + tid * 4);
    cp16(dst + (tid + 512) * 4,  src + (tid + 512) * 4);
    if (tid < 64) cp16(dst + (tid + 1024) * 4, src + (tid + 1024) * 4);
    asm volatile("cp.async.commit_group;" ::: "memory");
}

__device__ __forceinline__ void split_tf32(float x, uint32_t& hi, uint32_t& lo) {
    uint32_t u = __float_as_uint(x) & 0xffffe000u;
    float l = x - __uint_as_float(u);
    hi = u;
    lo = __float_as_uint(l) & 0xffffe000u;
}

__device__ __forceinline__ void mma8(float& d0, float& d1, float& d2, float& d3,
                                     uint32_t a0, uint32_t a1, uint32_t a2, uint32_t a3,
                                     uint32_t b0, uint32_t b1) {
    asm volatile(
        "mma.sync.aligned.m16n8k8.row.col.f32.tf32.tf32.f32 "
        "{%0,%1,%2,%3}, {%4,%5,%6,%7}, {%8,%9}, {%0,%1,%2,%3};"
        : "+f"(d0), "+f"(d1), "+f"(d2), "+f"(d3)
        : "r"(a0), "r"(a1), "r"(a2), "r"(a3), "r"(b0), "r"(b1));
}

// prep: build fused weights + pre-split into tf32 hi/lo chunk layout
__global__ void prep(const float* __restrict__ msg_w,
                     const float* __restrict__ upd_w) {
    const int kk = blockIdx.x, l = blockIdx.y, d = threadIdx.x;  // d = out col
    float v;
    if (kk < DIM) {
        v = upd_w[l * 2 * DIM * DIM + kk * DIM + d];
    } else {
        const float* M = msg_w + (l * DIM + (kk - DIM)) * DIM;
        const float* U2 = upd_w + l * 2 * DIM * DIM + DIM * DIM;
        v = 0.f;
        #pragma unroll 4
        for (int k = 0; k < DIM; k++) v = fmaf(M[k], U2[k * DIM + d], v);
    }
    uint32_t hi, lo;
    split_tf32(v, hi, lo);
    const int c = kk >> 4, kr = kk & 15;
    float* base = Wall_g + (l * 16 + c) * CHUNK_F;
    base[kr * WROW + d]          = __uint_as_float(hi);
    base[HALF_F + kr * WROW + d] = __uint_as_float(lo);
}

__global__ __launch_bounds__(512, 1)
void hexgnn_kernel(const float* __restrict__ x,
                   const float* __restrict__ in_w,  const float* __restrict__ in_b,
                   const float* __restrict__ in_g,  const float* __restrict__ in_beta,
                   const float* __restrict__ upd_b, const float* __restrict__ ln_g,
                   const float* __restrict__ ln_b,  const float* __restrict__ aq_w,
                   const float* __restrict__ aq_b,  const float* __restrict__ pp_w,
                   const float* __restrict__ pp_b,  const float* __restrict__ v1_w,
                   const float* __restrict__ v1_b,  const float* __restrict__ v2_w,
                   const float* __restrict__ v2_b,  const float* __restrict__ tf_w,
                   const float* __restrict__ tf_b,  float* __restrict__ out) {
    extern __shared__ char smraw[];
    Smem& sm = *reinterpret_cast<Smem*>(smraw);

    const int tid  = threadIdx.x;
    const int lane = tid & 31;
    const int warp = tid >> 5;
    const int qr   = lane >> 2;          // fragment groupID
    const int qc   = lane & 3;           // fragment threadID-in-group
    const int d0   = lane * 4;           // gather/embed: 4 cols per thread
    const int b    = blockIdx.x;
    const int B    = gridDim.x;
    // gather/embed node partition: warps 0-8 own 11, 9-15 own 10 (169 total)
    const int base = (warp < 9) ? warp * 11 : 99 + (warp - 9) * 10;
    const int ncnt = (warp < 9) ? 11 : 10;
    // mma tiles: t = warp + 16s; m-slab = t%11, n-group = t/11 (44 tiles)
    const int tcount = (warp < 12) ? 3 : 2;

    int rowoff[NBW];
    #pragma unroll
    for (int j = 0; j < NBW; j++) {
        int n = base + j; if (n > NN - 1) n = NN - 1;
        rowoff[j] = n * SROW;
    }

    // ---- adjacency tables + pad-row zeroing ----
    if (tid < NN) {
        const int i = tid / BOARD, j = tid % BOARD;
        const int di[6] = {1, -1, 0, 0, 1, -1};
        const int dj[6] = {0, 0, 1, -1, -1, 1};
        int cc = 0;
        for (int e = 0; e < 6; e++) {
            int ni = i + di[e], nj = j + dj[e];
            if (ni >= 0 && ni < BOARD && nj >= 0 && nj < BOARD)
                sm.nbr[tid * 6 + (cc++)] = ni * BOARD + nj;
        }
        sm.cnt[tid] = cc;
        sm.invdeg[tid] = 1.0f / (float)cc;
    }
    for (int i = tid; i < (NNP - NN) * SROW; i += 512) {   // zero pad rows once
        sm.h[NN * SROW + i] = 0.f;
        sm.hbar[NN * SROW + i] = 0.f;
    }

    // ---- input embedding: h = LN(gelu(x @ in_w + in_b)) ----
    {
        const float* xb = x + (size_t)b * CHN * NN;
        const float4 bi4 = *(const float4*)(in_b + d0);
        const float4 gg4 = *(const float4*)(in_g + d0);
        const float4 be4 = *(const float4*)(in_beta + d0);
        #pragma unroll 1
        for (int j = 0; j < NBW; j++) {
            if (j >= ncnt) break;
            const int n = (base + j);
            float a0 = bi4.x, a1 = bi4.y, a2 = bi4.z, a3 = bi4.w;
            #pragma unroll
            for (int ch = 0; ch < CHN; ch++) {
                const float xv = __ldg(xb + ch * NN + n);
                const float4 w = *(const float4*)(in_w + ch * DIM + d0);
                a0 = fmaf(xv, w.x, a0); a1 = fmaf(xv, w.y, a1);
                a2 = fmaf(xv, w.z, a2); a3 = fmaf(xv, w.w, a3);
            }
            float v0 = gelu_f(a0), v1 = gelu_f(a1), v2 = gelu_f(a2), v3 = gelu_f(a3);
            float ss = v0 + v1 + v2 + v3;
            float qq = v0*v0 + v1*v1 + v2*v2 + v3*v3;
            #pragma unroll
            for (int o = 16; o; o >>= 1) {
                ss += __shfl_xor_sync(0xffffffffu, ss, o);
                qq += __shfl_xor_sync(0xffffffffu, qq, o);
            }
            const float mu  = ss * (1.0f / DIM);
            const float var = qq * (1.0f / DIM) - mu * mu;
            const float rs  = rsqrtf(var + 1e-5f);
            *(float4*)(sm.h + rowoff[j] + d0) = make_float4(
                (v0 - mu) * rs * gg4.x + be4.x, (v1 - mu) * rs * gg4.y + be4.y,
                (v2 - mu) * rs * gg4.z + be4.z, (v3 - mu) * rs * gg4.w + be4.w);
        }
    }

    // ---- 8 GNN layers ----
    for (int l = 0; l < NLAYERS; l++) {
        __syncthreads();                              // h complete; prev wbuf reads done

        const float* WL = Wall_g + l * 16 * CHUNK_F;
        load_chunk(sm.u.wbuf[0], WL, tid);            // chunk 0 (overlaps gather)

        // neighbor-mean gather into hbar (own rows only)
        #pragma unroll 1
        for (int j = 0; j < NBW; j++) {
            if (j >= ncnt) break;
            const int n = base + j;
            const int c = sm.cnt[n];
            const int* nb = sm.nbr + n * 6;
            float s0 = 0.f, s1 = 0.f, s2 = 0.f, s3 = 0.f;
            for (int e = 0; e < c; e++) {
                const float4 m = *(const float4*)(sm.h + nb[e] * SROW + d0);
                s0 += m.x; s1 += m.y; s2 += m.z; s3 += m.w;
            }
            const float id = sm.invdeg[n];
            *(float4*)(sm.hbar + rowoff[j] + d0) =
                make_float4(s0 * id, s1 * id, s2 * id, s3 * id);
        }

        // ---- tensor-core GEMM: D[176 x 128] = [h|hbar] @ Wall, 3xTF32 ----
        float acc[3][4][4];
        #pragma unroll
        for (int s = 0; s < 3; s++)
            #pragma unroll
            for (int nt = 0; nt < 4; nt++)
                #pragma unroll
                for (int i = 0; i < 4; i++) acc[s][nt][i] = 0.f;

        #pragma unroll 1
        for (int c = 0; c < 16; c++) {
            asm volatile("cp.async.wait_group 0;" ::: "memory");
            __syncthreads();                  // chunk c visible; (c=0) gathers done
            if (c < 15) load_chunk(sm.u.wbuf[(c + 1) & 1], WL + (c + 1) * CHUNK_F, tid);

            const float* asrc = (c < 8) ? sm.h : sm.hbar;
            const int klocal = (c & 7) * 16;
            const float* wb = sm.u.wbuf[c & 1];

            #pragma unroll
            for (int s = 0; s < 3; s++) {
                if (s < tcount) {
                    const int t = warp + 16 * s;
                    const int m = t % 11, ng = t / 11;
                    const float* ap0 = asrc + (m * 16 + qr) * SROW + klocal + qc;
                    #pragma unroll
                    for (int ks = 0; ks < 2; ks++) {
                        const float* ap = ap0 + ks * 8;
                        uint32_t ah0, ah1, ah2, ah3, al0, al1, al2, al3;
                        split_tf32(ap[0],            ah0, al0);
                        split_tf32(ap[8 * SROW],     ah1, al1);
                        split_tf32(ap[4],            ah2, al2);
                        split_tf32(ap[8 * SROW + 4], ah3, al3);
                        const float* bph = wb + (ks * 8 + qc) * WROW + ng * 32 + qr;
                        const float* bpl = bph + HALF_F;
                        #pragma unroll
                        for (int nt = 0; nt < 4; nt++) {
                            const uint32_t bh0 = __float_as_uint(bph[nt * 8]);
                            const uint32_t bh1 = __float_as_uint(bph[nt * 8 + 4 * WROW]);
                            const uint32_t bl0 = __float_as_uint(bpl[nt * 8]);
                            const uint32_t bl1 = __float_as_uint(bpl[nt * 8 + 4 * WROW]);
                            mma8(acc[s][nt][0], acc[s][nt][1], acc[s][nt][2], acc[s][nt][3],
                                 ah0, ah1, ah2, ah3, bh0, bh1);
                            mma8(acc[s][nt][0], acc[s][nt][1], acc[s][nt][2], acc[s][nt][3],
                                 ah0, ah1, ah2, ah3, bl0, bl1);
                            mma8(acc[s][nt][0], acc[s][nt][1], acc[s][nt][2], acc[s][nt][3],
                                 al0, al1, al2, al3, bh0, bh1);
                        }
                    }
                }
            }
        }

        // ---- epilogue A: v = gelu(acc + bias) + h; per-node partials ----
        const float* ub = upd_b + l * DIM;
        #pragma unroll
        for (int s = 0; s < 3; s++) {
            if (s < tcount) {
                const int t = warp + 16 * s;
                const int m = t % 11, ng = t / 11;
                const int rlo = m * 16 + qr, rhi = rlo + 8;
                float sLo = 0.f, qLo = 0.f, sHi = 0.f, qHi = 0.f;
                #pragma unroll
                for (int nt = 0; nt < 4; nt++) {
                    const int c0 = ng * 32 + nt * 8 + qc * 2, c1 = c0 + 1;
                    const float u0 = __ldg(ub + c0), u1 = __ldg(ub + c1);
                    float v0 = gelu_f(acc[s][nt][0] + u0) + sm.h[rlo * SROW + c0];
                    float v1 = gelu_f(acc[s][nt][1] + u1) + sm.h[rlo * SROW + c1];
                    float v2 = gelu_f(acc[s][nt][2] + u0) + sm.h[rhi * SROW + c0];
                    float v3 = gelu_f(acc[s][nt][3] + u1) + sm.h[rhi * SROW + c1];
                    acc[s][nt][0] = v0; acc[s][nt][1] = v1;
                    acc[s][nt][2] = v2; acc[s][nt][3] = v3;
                    sLo += v0 + v1; qLo += v0 * v0 + v1 * v1;
                    sHi += v2 + v3; qHi += v2 * v2 + v3 * v3;
                }
                #pragma unroll
                for (int o = 1; o <= 2; o <<= 1) {   // reduce across quad (qc)
                    sLo += __shfl_xor_sync(0xffffffffu, sLo, o);
                    qLo += __shfl_xor_sync(0xffffffffu, qLo, o);
                    sHi += __shfl_xor_sync(0xffffffffu, sHi, o);
                    qHi += __shfl_xor_sync(0xffffffffu, qHi, o);
                }
                if (qc == 0) {
                    sm.lnpart[rlo * 8 + ng * 2]     = sLo;
                    sm.lnpart[rlo * 8 + ng * 2 + 1] = qLo;
                    sm.lnpart[rhi * 8 + ng * 2]     = sHi;
                    sm.lnpart[rhi * 8 + ng * 2 + 1] = qHi;
                }
            }
        }
        __syncthreads();                              // partials complete

        // ---- epilogue B: LayerNorm normalize + write h ----
        const float* lg = ln_g + l * DIM;
        const float* lb = ln_b + l * DIM;
        #pragma unroll
        for (int s = 0; s < 3; s++) {
            if (s < tcount) {
                const int t = warp + 16 * s;
                const int m = t % 11, ng = t / 11;
                const int rlo = m * 16 + qr, rhi = rlo + 8;
                const float* pl = sm.lnpart + rlo * 8;
                const float* ph = sm.lnpart + rhi * 8;
                const float sLo = pl[0] + pl[2] + pl[4] + pl[6];
                const float qLo = pl[1] + pl[3] + pl[5] + pl[7];
                const float sHi = ph[0] + ph[2] + ph[4] + ph[6];
                const float qHi = ph[1] + ph[3] + ph[5] + ph[7];
                const float muL = sLo * (1.0f / DIM);
                const float rsL = rsqrtf(qLo * (1.0f / DIM) - muL * muL + 1e-5f);
                const float muH = sHi * (1.0f / DIM);
                const float rsH = rsqrtf(qHi * (1.0f / DIM) - muH * muH + 1e-5f);
                #pragma unroll
                for (int nt = 0; nt < 4; nt++) {
                    const int c0 = ng * 32 + nt * 8 + qc * 2, c1 = c0 + 1;
                    const float g0 = __ldg(lg + c0), g1 = __ldg(lg + c1);
                    const float b0 = __ldg(lb + c0), b1 = __ldg(lb + c1);
                    if (rlo < NN) {
                        sm.h[rlo * SROW + c0] = (acc[s][nt][0] - muL) * rsL * g0 + b0;
                        sm.h[rlo * SROW + c1] = (acc[s][nt][1] - muL) * rsL * g1 + b1;
                    }
                    if (rhi < NN) {
                        sm.h[rhi * SROW + c0] = (acc[s][nt][2] - muH) * rsH * g0 + b0;
                        sm.h[rhi * SROW + c1] = (acc[s][nt][3] - muH) * rsH * g1 + b1;
                    }
                }
            }
        }
    }
    __syncthreads();

    // ---- heads (scratch lives in the wbuf union; wbuf is dead now) ----
    float* p_out = out;
    float* v_out = out + (size_t)B * NN;
    float* t_out = v_out + B;
    const float ppb = pp_b[0], aqb = aq_b[0], v2b = v2_b[0];

    for (int n = warp; n < NN; n += 16) {              // p + attention logits
        float hp = 0.f, ha = 0.f;
        #pragma unroll
        for (int i = 0; i < 4; i++) {
            const int dd = i * 32 + lane;
            const float hv = sm.h[n * SROW + dd];
            hp = fmaf(hv, pp_w[dd], hp);
            ha = fmaf(hv, aq_w[dd], ha);
        }
        #pragma unroll
        for (int o = 16; o; o >>= 1) {
            hp += __shfl_xor_sync(0xffffffffu, hp, o);
            ha += __shfl_xor_sync(0xffffffffu, ha, o);
        }
        if (lane == 0) { p_out[(size_t)b * NN + n] = hp + ppb; sm.u.hd.slog[n] = ha + aqb; }
    }
    __syncthreads();
    if (warp == 0) {                                   // softmax max
        float m = -3.4e38f;
        for (int n = lane; n < NN; n += 32) m = fmaxf(m, sm.u.hd.slog[n]);
        #pragma unroll
        for (int o = 16; o; o >>= 1) m = fmaxf(m, __shfl_xor_sync(0xffffffffu, m, o));
        if (lane == 0) sm.u.hd.scal[0] = m;
    }
    __syncthreads();
    if (tid < NN) sm.u.hd.slog[tid] = expf(sm.u.hd.slog[tid] - sm.u.hd.scal[0]);
    __syncthreads();
    if (warp == 0) {                                   // softmax Z
        float z = 0.f;
        for (int n = lane; n < NN; n += 32) z += sm.u.hd.slog[n];
        #pragma unroll
        for (int o = 16; o; o >>= 1) z += __shfl_xor_sync(0xffffffffu, z, o);
        if (lane == 0) sm.u.hd.scal[1] = z;
    }
    __syncthreads();
    {                                                  // g = sum_n h[n] * attn[n]
        const int q = tid >> 7, dc = tid & 127;
        const int ns = (q == 0) ? 0 : 43 + (q - 1) * 42;
        const int ne = ns + ((q == 0) ? 43 : 42);
        float gp = 0.f;
        for (int n = ns; n < ne; n++) gp = fmaf(sm.h[n * SROW + dc], sm.u.hd.slog[n], gp);
        sm.u.hd.gpart[q * DIM + dc] = gp;
    }
    __syncthreads();
    if (tid < DIM)
        sm.u.hd.gvec[tid] = (sm.u.hd.gpart[tid] + sm.u.hd.gpart[DIM + tid] +
                             sm.u.hd.gpart[2 * DIM + tid] + sm.u.hd.gpart[3 * DIM + tid])
                            / sm.u.hd.scal[1];
    __syncthreads();
    if (tid < 256) {                                   // v1
        float u = v1_b[tid];
        #pragma unroll 4
        for (int k = 0; k < DIM; k++) u = fmaf(sm.u.hd.gvec[k], v1_w[k * 256 + tid], u);
        sm.u.hd.uvec[tid] = gelu_f(u);
    }
    __syncthreads();
    if (tid < 256) {                                   // v2 reduce
        float pv = sm.u.hd.uvec[tid] * v2_w[tid];
        #pragma unroll
        for (int o = 16; o; o >>= 1) pv += __shfl_xor_sync(0xffffffffu, pv, o);
        if (lane == 0) sm.u.hd.redall[warp] = pv;
    }
    __syncthreads();
    if (tid == 0) {
        float sv = 0.f;
        #pragma unroll
        for (int w = 0; w < 8; w++) sv += sm.u.hd.redall[w];
        v_out[b] = tanhf(sv + v2b);
    }
    if (warp < 4) {                                    // t head
        float tp = 0.f;
        #pragma unroll
        for (int i = 0; i < 4; i++) {
            const int dd = i * 32 + lane;
            tp = fmaf(sm.u.hd.gvec[dd], tf_w[dd * 4 + warp], tp);
        }
        #pragma unroll
        for (int o = 16; o; o >>= 1) tp += __shfl_xor_sync(0xffffffffu, tp, o);
        if (lane == 0) t_out[(size_t)b * 4 + warp] = tp + tf_b[warp];
    }
}

extern "C" void kernel_launch(void* const* d_in, const int* in_sizes, int n_in,
                              void* d_out, int out_size) {
    const float* x       = (const float*)d_in[0];
    // d_in[1]=src, d_in[2]=dst: fixed hex adjacency, recomputed in-kernel
    const float* in_w    = (const float*)d_in[3];
    const float* in_b    = (const float*)d_in[4];
    const float* in_g    = (const float*)d_in[5];
    const float* in_beta = (const float*)d_in[6];
    const float* msg_w   = (const float*)d_in[7];
    const float* upd_w   = (const float*)d_in[8];
    const float* upd_b   = (const float*)d_in[9];
    const float* ln_g    = (const float*)d_in[10];
    const float* ln_b    = (const float*)d_in[11];
    const float* aq_w    = (const float*)d_in[12];
    const float* aq_b    = (const float*)d_in[13];
    const float* pp_w    = (const float*)d_in[14];
    const float* pp_b    = (const float*)d_in[15];
    const float* v1_w    = (const float*)d_in[16];
    const float* v1_b    = (const float*)d_in[17];
    const float* v2_w    = (const float*)d_in[18];
    const float* v2_b    = (const float*)d_in[19];
    const float* tf_w    = (const float*)d_in[20];
    const float* tf_b    = (const float*)d_in[21];
    float* out = (float*)d_out;

    const int B = in_sizes[0] / (CHN * NN);   // 512

    prep<<<dim3(256, NLAYERS), DIM>>>(msg_w, upd_w);

    const size_t smem = sizeof(Smem);
    cudaFuncSetAttribute(hexgnn_kernel, cudaFuncAttributeMaxDynamicSharedMemorySize,
                         (int)smem);
    hexgnn_kernel<<<B, 512, smem>>>(x, in_w, in_b, in_g, in_beta, upd_b,
                                    ln_g, ln_b, aq_w, aq_b, pp_w, pp_b, v1_w, v1_b,
                                    v2_w, v2_b, tf_w, tf_b, out);
}